// round 4
// baseline (speedup 1.0000x reference)
#include <cuda_runtime.h>
#include <cuda_bf16.h>
#include <math.h>

#define N_NODES 50000
#define N_EDGES 800000
#define IN_DIM  128
#define FEAT    64

// ---------------- scratch (static device globals; no allocation) ----------------
// Accessed directly from kernels via selectors: kernel_launch makes NO runtime
// API calls other than kernel launches (strict graph-capture safety).
__device__ float g_H0[N_NODES * FEAT];
__device__ float g_H1[N_NODES * FEAT];
__device__ float g_Y [N_NODES * 3 * FEAT];   // [N, 3, 64]
__device__ float g_acc[N_NODES * FEAT];
__device__ int   g_cnt[N_NODES];

__device__ __forceinline__ float* sel_buf(int s) {
    // 0 -> H0, 1 -> H1 (ping-pong hidden states)
    return (s == 0) ? g_H0 : g_H1;
}

// ---------------- utility kernels ----------------
__global__ void zero_acc_kernel() {
    int i = blockIdx.x * blockDim.x + threadIdx.x;
    if (i < N_NODES * FEAT) g_acc[i] = 0.0f;
}
__global__ void zero_cnt_kernel() {
    int i = blockIdx.x * blockDim.x + threadIdx.x;
    if (i < N_NODES) g_cnt[i] = 0;
}

// count in-degree: cnt[tgt[e]] += 1
__global__ void count_kernel(const int* __restrict__ ei) {
    int e = blockIdx.x * blockDim.x + threadIdx.x;
    if (e < N_EDGES) atomicAdd(&g_cnt[ei[N_EDGES + e]], 1);
}

// ---------------- node-side GEMM ----------------
// Computes C[row, coff+o] = sum_k A[row,k] * B[c*K*64 + k*64 + o] (+bias[o]).
// A source: external pointer (asel<0) or ping-pong buffer (asel in {0,1}).
// C dest:   g_Y (csel==2, ldc=192) or ping-pong buffer (csel in {0,1}, ldc=64).
// Block tile 64x64, 256 threads, 4x4 register tile.
__global__ void gemm_nodes(const float* __restrict__ Aext, int asel, int K,
                           const float* __restrict__ B,
                           const float* __restrict__ bias,
                           int csel, int ldc)
{
    __shared__ float As[64 * 68];   // transposed, padded stride 68
    __shared__ float Ws[64 * 64];

    const float* A = (asel < 0) ? Aext : sel_buf(asel);
    float* C = (csel == 2) ? g_Y : sel_buf(csel);

    const int nblk = blockIdx.x * 64;
    const float* Bb = B + (size_t)blockIdx.y * K * 64;
    const int coff = blockIdx.y * 64;

    const int tid = threadIdx.x;
    const int tx = tid & 15;        // out group  (4 cols)
    const int ty = tid >> 4;        // node group (4 rows)

    float acc[4][4] = {};

    for (int k0 = 0; k0 < K; k0 += 64) {
        #pragma unroll 4
        for (int i = tid; i < 4096; i += 256) {
            int n = i >> 6, k = i & 63;
            int row = nblk + n;
            As[k * 68 + n] = (row < N_NODES) ? A[(size_t)row * K + k0 + k] : 0.0f;
        }
        #pragma unroll 4
        for (int i = tid; i < 4096; i += 256) {
            int k = i >> 6;
            Ws[i] = Bb[(size_t)(k0 + k) * 64 + (i & 63)];
        }
        __syncthreads();

        #pragma unroll
        for (int kk = 0; kk < 64; kk++) {
            float4 a4 = *(const float4*)&As[kk * 68 + ty * 4];
            float4 b4 = *(const float4*)&Ws[kk * 64 + tx * 4];
            float av[4] = {a4.x, a4.y, a4.z, a4.w};
            float bv[4] = {b4.x, b4.y, b4.z, b4.w};
            #pragma unroll
            for (int i = 0; i < 4; i++)
                #pragma unroll
                for (int j = 0; j < 4; j++)
                    acc[i][j] += av[i] * bv[j];
        }
        __syncthreads();
    }

    #pragma unroll
    for (int i = 0; i < 4; i++) {
        int row = nblk + ty * 4 + i;
        if (row >= N_NODES) continue;
        #pragma unroll
        for (int j = 0; j < 4; j++) {
            int o = tx * 4 + j;
            float v = acc[i][j];
            if (bias) v += bias[o];
            C[(size_t)row * ldc + coff + o] = v;
        }
    }
}

// ---------------- edge scatter ----------------
// m[o] = ea0*Y[src,0,o] + ea1*Y[src,1,o] + ea2*Y[src,2,o];  acc[tgt,o] += m[o]
// 16 threads per edge, each thread handles 4 contiguous outputs via float4
// loads (Y fits in L2) + 4 atomicAdds (resolve in L2).
__global__ void edge_scatter(const int* __restrict__ ei,
                             const float* __restrict__ ea)
{
    int e = blockIdx.x * 16 + (threadIdx.x >> 4);
    if (e >= N_EDGES) return;
    int o = (threadIdx.x & 15) * 4;
    int j = __ldg(&ei[e]);
    int i = __ldg(&ei[N_EDGES + e]);
    float a0 = __ldg(&ea[(size_t)e * 3 + 0]);
    float a1 = __ldg(&ea[(size_t)e * 3 + 1]);
    float a2 = __ldg(&ea[(size_t)e * 3 + 2]);
    const float* yj = g_Y + (size_t)j * 192 + o;
    float4 y0 = *(const float4*)(yj);
    float4 y1 = *(const float4*)(yj + 64);
    float4 y2 = *(const float4*)(yj + 128);
    float m0 = a0 * y0.x + a1 * y1.x + a2 * y2.x;
    float m1 = a0 * y0.y + a1 * y1.y + a2 * y2.y;
    float m2 = a0 * y0.z + a1 * y1.z + a2 * y2.z;
    float m3 = a0 * y0.w + a1 * y1.w + a2 * y2.w;
    float* dst = g_acc + (size_t)i * 64 + o;
    atomicAdd(dst + 0, m0);
    atomicAdd(dst + 1, m1);
    atomicAdd(dst + 2, m2);
    atomicAdd(dst + 3, m3);
}

// ---------------- epilogue: mean + bias (+relu) ----------------
__global__ void finish_kernel(const float* __restrict__ bias, int outsel, int do_relu)
{
    int idx = blockIdx.x * blockDim.x + threadIdx.x;
    if (idx >= N_NODES * FEAT) return;
    int i = idx >> 6, o = idx & 63;
    float inv = 1.0f / fmaxf((float)g_cnt[i], 1.0f);
    float v = g_acc[idx] * inv + bias[o];
    if (do_relu) v = fmaxf(v, 0.0f);
    sel_buf(outsel)[idx] = v;
}

// ---------------- final L2 normalize ----------------
__global__ void normalize_kernel(int insel, float* __restrict__ out)
{
    int node = blockIdx.x * 8 + (threadIdx.x >> 5);
    if (node >= N_NODES) return;
    const float* h = sel_buf(insel);
    int lane = threadIdx.x & 31;
    size_t base = (size_t)node * 64;
    float v0 = h[base + lane];
    float v1 = h[base + lane + 32];
    float s = v0 * v0 + v1 * v1;
    #pragma unroll
    for (int off = 16; off > 0; off >>= 1)
        s += __shfl_xor_sync(0xFFFFFFFFu, s, off);
    float inv = 1.0f / fmaxf(sqrtf(s), 1e-12f);
    out[base + lane]      = v0 * inv;
    out[base + lane + 32] = v1 * inv;
}

// ---------------- launch (kernel launches ONLY — graph-capture safe) ----------------
extern "C" void kernel_launch(void* const* d_in, const int* in_sizes, int n_in,
                              void* d_out, int out_size)
{
    const float* x     = (const float*)d_in[0];
    const int*   ei    = (const int*)  d_in[1];   // [2, E]
    const float* ea    = (const float*)d_in[2];   // [E, 3]
    const float* pre_w = (const float*)d_in[3];   // [128, 64]
    const float* pre_b = (const float*)d_in[4];   // [64]
    const float* w[3]  = {(const float*)d_in[5], (const float*)d_in[7], (const float*)d_in[9]};
    const float* b[3]  = {(const float*)d_in[6], (const float*)d_in[8], (const float*)d_in[10]};
    float* out = (float*)d_out;

    const int gemm_blocks = (N_NODES + 63) / 64;   // 782

    // in-degree counts (shared by all 3 layers)
    zero_cnt_kernel<<<(N_NODES + 255) / 256, 256>>>();
    count_kernel<<<(N_EDGES + 255) / 256, 256>>>(ei);

    // linear_pre: H0 = x @ pre_w + pre_b
    gemm_nodes<<<dim3(gemm_blocks, 1), 256>>>(x, -1, IN_DIM, pre_w, pre_b, 0, 64);

    int hin = 0, hout = 1;
    for (int l = 0; l < 3; l++) {
        // Y[j, c, o] = (H_in @ W_c)[j, o]  for c = 0..2
        gemm_nodes<<<dim3(gemm_blocks, 3), 256>>>(nullptr, hin, FEAT, w[l], nullptr, 2, 192);
        zero_acc_kernel<<<(N_NODES * FEAT + 255) / 256, 256>>>();
        edge_scatter<<<(N_EDGES + 15) / 16, 256>>>(ei, ea);
        finish_kernel<<<(N_NODES * FEAT + 255) / 256, 256>>>(b[l], hout, (l < 2) ? 1 : 0);
        int t = hin; hin = hout; hout = t;
    }

    // hin now holds layer-3 output; L2-normalize into d_out
    normalize_kernel<<<(N_NODES + 7) / 8, 256>>>(hin, out);
}

// round 5
// speedup vs baseline: 1.6334x; 1.6334x over previous
#include <cuda_runtime.h>
#include <cuda_bf16.h>
#include <math.h>

#define N_NODES 50000
#define N_EDGES 800000
#define IN_DIM  128
#define FEAT    64
#define SCAN_BLOCKS 196   // ceil(50001/256)

// ---------------- scratch (static device globals; no allocation) ----------------
__device__ float g_H0[N_NODES * FEAT];
__device__ float g_H1[N_NODES * FEAT];
__device__ float g_Y [N_NODES * 3 * FEAT];   // [N, 3, 64]
__device__ int   g_cnt[N_NODES];
__device__ int   g_off[N_NODES + 1];
__device__ int   g_pos[N_NODES];
__device__ int   g_csr[N_EDGES];
__device__ int   g_bsum[256];

__device__ __forceinline__ float* sel_buf(int s) {
    return (s == 0) ? g_H0 : g_H1;
}

// ---------------- CSR build (once per launch) ----------------
__global__ void zero_cnt_kernel() {
    int i = blockIdx.x * blockDim.x + threadIdx.x;
    if (i < N_NODES) g_cnt[i] = 0;
}
__global__ void count_kernel(const int* __restrict__ ei) {
    int e = blockIdx.x * blockDim.x + threadIdx.x;
    if (e < N_EDGES) atomicAdd(&g_cnt[ei[N_EDGES + e]], 1);
}
// block-local exclusive scan + block sums
__global__ void scan1_kernel() {
    __shared__ int s[256];
    int t = threadIdx.x, i = blockIdx.x * 256 + t;
    int v = (i < N_NODES) ? g_cnt[i] : 0;
    s[t] = v; __syncthreads();
    #pragma unroll
    for (int d = 1; d < 256; d <<= 1) {
        int x = (t >= d) ? s[t - d] : 0;
        __syncthreads();
        s[t] += x;
        __syncthreads();
    }
    if (i < N_NODES) g_off[i] = s[t] - v;      // exclusive within block
    if (t == 255) g_bsum[blockIdx.x] = s[255]; // block total
}
// exclusive scan of the block sums (single block)
__global__ void scan2_kernel() {
    __shared__ int s[256];
    int t = threadIdx.x;
    int v = (t < SCAN_BLOCKS) ? g_bsum[t] : 0;
    s[t] = v; __syncthreads();
    #pragma unroll
    for (int d = 1; d < 256; d <<= 1) {
        int x = (t >= d) ? s[t - d] : 0;
        __syncthreads();
        s[t] += x;
        __syncthreads();
    }
    if (t < SCAN_BLOCKS) g_bsum[t] = s[t] - v;
}
// add block offsets; init write cursors; set sentinel
__global__ void scan3_kernel() {
    int i = blockIdx.x * 256 + threadIdx.x;
    if (i < N_NODES) {
        int o = g_off[i] + g_bsum[i >> 8];
        g_off[i] = o;
        g_pos[i] = o;
    }
    if (i == N_NODES) g_off[N_NODES] = N_EDGES;
}
__global__ void fill_csr_kernel(const int* __restrict__ ei) {
    int e = blockIdx.x * blockDim.x + threadIdx.x;
    if (e < N_EDGES) {
        int t = ei[N_EDGES + e];
        int slot = atomicAdd(&g_pos[t], 1);
        g_csr[slot] = e;
    }
}

// ---------------- node-side GEMM ----------------
// C[row, 64*by + o] = sum_k A[row,k] * B[by*K*64 + k*64 + o] (+bias[o]).
// Block tile 64x64, 256 threads, 4x4 register tile.
__global__ void gemm_nodes(const float* __restrict__ Aext, int asel, int K,
                           const float* __restrict__ B,
                           const float* __restrict__ bias,
                           int csel, int ldc)
{
    __shared__ float As[64 * 68];
    __shared__ float Ws[64 * 64];

    const float* A = (asel < 0) ? Aext : sel_buf(asel);
    float* C = (csel == 2) ? g_Y : sel_buf(csel);

    const int nblk = blockIdx.x * 64;
    const float* Bb = B + (size_t)blockIdx.y * K * 64;
    const int coff = blockIdx.y * 64;

    const int tid = threadIdx.x;
    const int tx = tid & 15;
    const int ty = tid >> 4;

    float acc[4][4] = {};

    for (int k0 = 0; k0 < K; k0 += 64) {
        #pragma unroll 4
        for (int i = tid; i < 4096; i += 256) {
            int n = i >> 6, k = i & 63;
            int row = nblk + n;
            As[k * 68 + n] = (row < N_NODES) ? A[(size_t)row * K + k0 + k] : 0.0f;
        }
        #pragma unroll 4
        for (int i = tid; i < 4096; i += 256) {
            int k = i >> 6;
            Ws[i] = Bb[(size_t)(k0 + k) * 64 + (i & 63)];
        }
        __syncthreads();

        #pragma unroll
        for (int kk = 0; kk < 64; kk++) {
            float4 a4 = *(const float4*)&As[kk * 68 + ty * 4];
            float4 b4 = *(const float4*)&Ws[kk * 64 + tx * 4];
            float av[4] = {a4.x, a4.y, a4.z, a4.w};
            float bv[4] = {b4.x, b4.y, b4.z, b4.w};
            #pragma unroll
            for (int i = 0; i < 4; i++)
                #pragma unroll
                for (int j = 0; j < 4; j++)
                    acc[i][j] += av[i] * bv[j];
        }
        __syncthreads();
    }

    #pragma unroll
    for (int i = 0; i < 4; i++) {
        int row = nblk + ty * 4 + i;
        if (row >= N_NODES) continue;
        #pragma unroll
        for (int j = 0; j < 4; j++) {
            int o = tx * 4 + j;
            float v = acc[i][j];
            if (bias) v += bias[o];
            C[(size_t)row * ldc + coff + o] = v;
        }
    }
}

// ---------------- gather aggregation (warp per node, no atomics) ----------------
// For node i: out[i,o] = relu?( (1/max(deg,1)) * sum_{e in in(i)} sum_c ea[e,c]*Y[src_e,c,o] + b[o] )
// Optionally fused final L2-normalize. Lane handles o = lane and o = lane+32.
__global__ void gather_kernel(const int* __restrict__ ei,
                              const float* __restrict__ ea,
                              const float* __restrict__ bias,
                              int do_relu, int do_norm,
                              int outsel, float* __restrict__ extout)
{
    int node = blockIdx.x * 8 + (threadIdx.x >> 5);
    if (node >= N_NODES) return;
    int lane = threadIdx.x & 31;
    int off = g_off[node];
    int deg = g_off[node + 1] - off;

    float s0 = 0.0f, s1 = 0.0f;
    for (int base = 0; base < deg; base += 32) {
        int   mysrc = 0;
        float ma0 = 0.0f, ma1 = 0.0f, ma2 = 0.0f;
        if (base + lane < deg) {
            int eid = __ldg(&g_csr[off + base + lane]);
            mysrc = __ldg(&ei[eid]);
            ma0 = __ldg(&ea[(size_t)eid * 3 + 0]);
            ma1 = __ldg(&ea[(size_t)eid * 3 + 1]);
            ma2 = __ldg(&ea[(size_t)eid * 3 + 2]);
        }
        int m = min(32, deg - base);
        for (int k = 0; k < m; k++) {
            int   src = __shfl_sync(0xffffffffu, mysrc, k);
            float a0  = __shfl_sync(0xffffffffu, ma0, k);
            float a1  = __shfl_sync(0xffffffffu, ma1, k);
            float a2  = __shfl_sync(0xffffffffu, ma2, k);
            const float* y = g_Y + (size_t)src * 192;
            float y00 = __ldg(&y[lane]);
            float y01 = __ldg(&y[64 + lane]);
            float y02 = __ldg(&y[128 + lane]);
            float y10 = __ldg(&y[32 + lane]);
            float y11 = __ldg(&y[96 + lane]);
            float y12 = __ldg(&y[160 + lane]);
            s0 += a0 * y00 + a1 * y01 + a2 * y02;
            s1 += a0 * y10 + a1 * y11 + a2 * y12;
        }
    }

    float inv = 1.0f / fmaxf((float)deg, 1.0f);
    s0 = s0 * inv + __ldg(&bias[lane]);
    s1 = s1 * inv + __ldg(&bias[lane + 32]);
    if (do_relu) { s0 = fmaxf(s0, 0.0f); s1 = fmaxf(s1, 0.0f); }
    if (do_norm) {
        float ss = s0 * s0 + s1 * s1;
        #pragma unroll
        for (int d = 16; d > 0; d >>= 1)
            ss += __shfl_xor_sync(0xffffffffu, ss, d);
        float r = 1.0f / fmaxf(sqrtf(ss), 1e-12f);
        s0 *= r; s1 *= r;
    }

    float* out = (outsel >= 0) ? sel_buf(outsel) : extout;
    out[(size_t)node * 64 + lane]      = s0;
    out[(size_t)node * 64 + lane + 32] = s1;
}

// ---------------- launch (kernel launches ONLY — graph-capture safe) ----------------
extern "C" void kernel_launch(void* const* d_in, const int* in_sizes, int n_in,
                              void* d_out, int out_size)
{
    const float* x     = (const float*)d_in[0];
    const int*   ei    = (const int*)  d_in[1];   // [2, E]
    const float* ea    = (const float*)d_in[2];   // [E, 3]
    const float* pre_w = (const float*)d_in[3];   // [128, 64]
    const float* pre_b = (const float*)d_in[4];   // [64]
    const float* w[3]  = {(const float*)d_in[5], (const float*)d_in[7], (const float*)d_in[9]};
    const float* b[3]  = {(const float*)d_in[6], (const float*)d_in[8], (const float*)d_in[10]};
    float* out = (float*)d_out;

    const int gemm_blocks = (N_NODES + 63) / 64;   // 782

    // ---- CSR build (once; graph is fixed per launch) ----
    zero_cnt_kernel<<<(N_NODES + 255) / 256, 256>>>();
    count_kernel<<<(N_EDGES + 255) / 256, 256>>>(ei);
    scan1_kernel<<<SCAN_BLOCKS, 256>>>();
    scan2_kernel<<<1, 256>>>();
    scan3_kernel<<<SCAN_BLOCKS, 256>>>();
    fill_csr_kernel<<<(N_EDGES + 255) / 256, 256>>>(ei);

    // linear_pre: H0 = x @ pre_w + pre_b
    gemm_nodes<<<dim3(gemm_blocks, 1), 256>>>(x, -1, IN_DIM, pre_w, pre_b, 0, 64);

    int hin = 0, hout = 1;
    for (int l = 0; l < 3; l++) {
        // Y[j, c, o] = (H_in @ W_c)[j, o]  for c = 0..2
        gemm_nodes<<<dim3(gemm_blocks, 3), 256>>>(nullptr, hin, FEAT, w[l], nullptr, 2, 192);
        // aggregate + mean + bias (+relu for l<2, +L2-normalize for l==2)
        if (l < 2) {
            gather_kernel<<<(N_NODES + 7) / 8, 256>>>(ei, ea, b[l], 1, 0, hout, nullptr);
        } else {
            gather_kernel<<<(N_NODES + 7) / 8, 256>>>(ei, ea, b[l], 0, 1, -1, out);
        }
        int t = hin; hin = hout; hout = t;
    }
}

// round 6
// speedup vs baseline: 1.8224x; 1.1157x over previous
#include <cuda_runtime.h>
#include <cuda_bf16.h>
#include <math.h>

#define N_NODES 50000
#define N_EDGES 800000
#define IN_DIM  128
#define FEAT    64
#define SCAN_BLOCKS 196   // ceil(50001/256)

// ---------------- scratch (static device globals; no allocation) ----------------
__device__ float g_H0[N_NODES * FEAT];
__device__ float g_H1[N_NODES * FEAT];
__device__ float g_Agg[N_NODES * 192];   // aggregated messages [N, 3, 64]
__device__ int   g_cnt[N_NODES];
__device__ int   g_off[N_NODES + 1];
__device__ int   g_pos[N_NODES];
__device__ int   g_csr[N_EDGES];
__device__ int   g_bsum[256];

__device__ __forceinline__ float* sel_buf(int s) {
    return (s == 0) ? g_H0 : g_H1;
}

// ---------------- CSR build (once per launch) ----------------
__global__ void zero_cnt_kernel() {
    int i = blockIdx.x * blockDim.x + threadIdx.x;
    if (i < N_NODES) g_cnt[i] = 0;
}
__global__ void count_kernel(const int* __restrict__ ei) {
    int e = blockIdx.x * blockDim.x + threadIdx.x;
    if (e < N_EDGES) atomicAdd(&g_cnt[ei[N_EDGES + e]], 1);
}
__global__ void scan1_kernel() {
    __shared__ int s[256];
    int t = threadIdx.x, i = blockIdx.x * 256 + t;
    int v = (i < N_NODES) ? g_cnt[i] : 0;
    s[t] = v; __syncthreads();
    #pragma unroll
    for (int d = 1; d < 256; d <<= 1) {
        int x = (t >= d) ? s[t - d] : 0;
        __syncthreads();
        s[t] += x;
        __syncthreads();
    }
    if (i < N_NODES) g_off[i] = s[t] - v;
    if (t == 255) g_bsum[blockIdx.x] = s[255];
}
__global__ void scan2_kernel() {
    __shared__ int s[256];
    int t = threadIdx.x;
    int v = (t < SCAN_BLOCKS) ? g_bsum[t] : 0;
    s[t] = v; __syncthreads();
    #pragma unroll
    for (int d = 1; d < 256; d <<= 1) {
        int x = (t >= d) ? s[t - d] : 0;
        __syncthreads();
        s[t] += x;
        __syncthreads();
    }
    if (t < SCAN_BLOCKS) g_bsum[t] = s[t] - v;
}
__global__ void scan3_kernel() {
    int i = blockIdx.x * 256 + threadIdx.x;
    if (i < N_NODES) {
        int o = g_off[i] + g_bsum[i >> 8];
        g_off[i] = o;
        g_pos[i] = o;
    }
    if (i == N_NODES) g_off[N_NODES] = N_EDGES;
}
__global__ void fill_csr_kernel(const int* __restrict__ ei) {
    int e = blockIdx.x * blockDim.x + threadIdx.x;
    if (e < N_EDGES) {
        int t = ei[N_EDGES + e];
        int slot = atomicAdd(&g_pos[t], 1);
        g_csr[slot] = e;
    }
}

// ---------------- edge aggregation (warp per node, gathers h: 256 B/edge) ----------
// g_Agg[i, c*64+f] = (1/max(deg,1)) * sum_{e in in(i)} ea[e,c] * h[src_e, f]
__global__ void agg_kernel(const int* __restrict__ ei,
                           const float* __restrict__ ea,
                           int hsel)
{
    int node = blockIdx.x * 8 + (threadIdx.x >> 5);
    if (node >= N_NODES) return;
    int lane = threadIdx.x & 31;
    const float* H = sel_buf(hsel);
    int off = g_off[node];
    int deg = g_off[node + 1] - off;

    float s0x = 0.f, s0y = 0.f, s1x = 0.f, s1y = 0.f, s2x = 0.f, s2y = 0.f;

    for (int base = 0; base < deg; base += 32) {
        int   mysrc = 0;
        float ma0 = 0.f, ma1 = 0.f, ma2 = 0.f;
        if (base + lane < deg) {
            int eid = __ldg(&g_csr[off + base + lane]);
            mysrc = __ldg(&ei[eid]);
            ma0 = __ldg(&ea[(size_t)eid * 3 + 0]);
            ma1 = __ldg(&ea[(size_t)eid * 3 + 1]);
            ma2 = __ldg(&ea[(size_t)eid * 3 + 2]);
        }
        int m = min(32, deg - base);
        for (int k = 0; k < m; k++) {
            int   src = __shfl_sync(0xffffffffu, mysrc, k);
            float a0  = __shfl_sync(0xffffffffu, ma0, k);
            float a1  = __shfl_sync(0xffffffffu, ma1, k);
            float a2  = __shfl_sync(0xffffffffu, ma2, k);
            float2 hv = __ldg(&((const float2*)(H + (size_t)src * 64))[lane]);
            s0x += a0 * hv.x; s0y += a0 * hv.y;
            s1x += a1 * hv.x; s1y += a1 * hv.y;
            s2x += a2 * hv.x; s2y += a2 * hv.y;
        }
    }

    float inv = 1.0f / fmaxf((float)deg, 1.0f);
    float* out = g_Agg + (size_t)node * 192;
    ((float2*)(out      ))[lane] = make_float2(s0x * inv, s0y * inv);
    ((float2*)(out +  64))[lane] = make_float2(s1x * inv, s1y * inv);
    ((float2*)(out + 128))[lane] = make_float2(s2x * inv, s2y * inv);
}

// ---------------- node-side GEMM, fused epilogue ----------------
// C[row, o] = sum_k A[row,k] * B[k,o] + bias[o]; optional relu; optional row L2-norm.
// Block: 128 rows x 64 cols, 256 threads, 8x4 register tile, k-chunk 32.
// A in smem non-transposed, stride 36 (+4-float skew per 8 rows), float4 reads along k.
#define AS_STRIDE 36
__device__ __forceinline__ int arow(int n) { return n * AS_STRIDE + ((n >> 3) << 2); }

__global__ void __launch_bounds__(256)
gemm_nodes(const float* __restrict__ Aext, int asel, int K,
           const float* __restrict__ B, const float* __restrict__ bias,
           int do_relu, int do_norm, int csel, float* __restrict__ extout)
{
    __shared__ float As[128 * AS_STRIDE + 64];
    __shared__ float Ws[32 * 64];

    const float* A = (asel < 0) ? Aext : ((asel == 2) ? g_Agg : sel_buf(asel));
    float* C = (csel < 0) ? extout : sel_buf(csel);

    const int nblk = blockIdx.x * 128;
    const int tid = threadIdx.x;
    const int tx = tid & 15;     // 4 cols each
    const int ty = tid >> 4;     // 8 rows each

    float acc[8][4] = {};

    for (int k0 = 0; k0 < K; k0 += 32) {
        // load A chunk [128 rows x 32 k] row-major (coalesced, conflict-free store)
        #pragma unroll
        for (int i = tid; i < 4096; i += 256) {
            int n = i >> 5, k = i & 31;
            int row = nblk + n;
            As[arow(n) + k] = (row < N_NODES) ? A[(size_t)row * K + k0 + k] : 0.0f;
        }
        // load B chunk [32 k x 64 o]
        #pragma unroll
        for (int i = tid; i < 2048; i += 256) {
            Ws[i] = B[(size_t)(k0 + (i >> 6)) * 64 + (i & 63)];
        }
        __syncthreads();

        #pragma unroll
        for (int kk = 0; kk < 32; kk += 4) {
            float4 a[8];
            #pragma unroll
            for (int i = 0; i < 8; i++)
                a[i] = *(const float4*)&As[arow(ty * 8 + i) + kk];
            #pragma unroll
            for (int q = 0; q < 4; q++) {
                float4 b4 = *(const float4*)&Ws[(kk + q) * 64 + tx * 4];
                float bv[4] = {b4.x, b4.y, b4.z, b4.w};
                #pragma unroll
                for (int i = 0; i < 8; i++) {
                    float av = (q == 0) ? a[i].x : (q == 1) ? a[i].y : (q == 2) ? a[i].z : a[i].w;
                    #pragma unroll
                    for (int j = 0; j < 4; j++)
                        acc[i][j] += av * bv[j];
                }
            }
        }
        __syncthreads();
    }

    float bb[4];
    #pragma unroll
    for (int j = 0; j < 4; j++) bb[j] = __ldg(&bias[tx * 4 + j]);

    #pragma unroll
    for (int i = 0; i < 8; i++) {
        int row = nblk + ty * 8 + i;
        float v[4];
        #pragma unroll
        for (int j = 0; j < 4; j++) {
            v[j] = acc[i][j] + bb[j];
            if (do_relu) v[j] = fmaxf(v[j], 0.0f);
        }
        if (do_norm) {
            // row's 64 outputs live on the 16 same-ty lanes (a half-warp):
            // shfl_xor masks 1,2,4,8 reduce exactly within that group.
            float ss = v[0] * v[0] + v[1] * v[1] + v[2] * v[2] + v[3] * v[3];
            #pragma unroll
            for (int msk = 1; msk < 16; msk <<= 1)
                ss += __shfl_xor_sync(0xffffffffu, ss, msk);
            float r = 1.0f / fmaxf(sqrtf(ss), 1e-12f);
            #pragma unroll
            for (int j = 0; j < 4; j++) v[j] *= r;
        }
        if (row < N_NODES)
            *(float4*)&C[(size_t)row * 64 + tx * 4] = make_float4(v[0], v[1], v[2], v[3]);
    }
}

// ---------------- launch (kernel launches ONLY — graph-capture safe) ----------------
extern "C" void kernel_launch(void* const* d_in, const int* in_sizes, int n_in,
                              void* d_out, int out_size)
{
    const float* x     = (const float*)d_in[0];
    const int*   ei    = (const int*)  d_in[1];   // [2, E]
    const float* ea    = (const float*)d_in[2];   // [E, 3]
    const float* pre_w = (const float*)d_in[3];   // [128, 64]
    const float* pre_b = (const float*)d_in[4];   // [64]
    const float* w[3]  = {(const float*)d_in[5], (const float*)d_in[7], (const float*)d_in[9]};
    const float* b[3]  = {(const float*)d_in[6], (const float*)d_in[8], (const float*)d_in[10]};
    float* out = (float*)d_out;

    const int gemm_blocks = (N_NODES + 127) / 128;   // 391

    // ---- CSR build (once; graph is fixed per launch) ----
    zero_cnt_kernel<<<(N_NODES + 255) / 256, 256>>>();
    count_kernel<<<(N_EDGES + 255) / 256, 256>>>(ei);
    scan1_kernel<<<SCAN_BLOCKS, 256>>>();
    scan2_kernel<<<1, 256>>>();
    scan3_kernel<<<SCAN_BLOCKS, 256>>>();
    fill_csr_kernel<<<(N_EDGES + 255) / 256, 256>>>(ei);

    // linear_pre: H0 = x @ pre_w + pre_b
    gemm_nodes<<<gemm_blocks, 256>>>(x, -1, IN_DIM, pre_w, pre_b, 0, 0, 0, nullptr);

    int hin = 0, hout = 1;
    for (int l = 0; l < 3; l++) {
        // aggregate h (+ mean) -> g_Agg [N, 192]
        agg_kernel<<<(N_NODES + 7) / 8, 256>>>(ei, ea, hin);
        // Hout = g_Agg @ W + b  (+relu for l<2; +L2-normalize into d_out for l==2)
        if (l < 2) {
            gemm_nodes<<<gemm_blocks, 256>>>(nullptr, 2, 192, w[l], b[l], 1, 0, hout, nullptr);
        } else {
            gemm_nodes<<<gemm_blocks, 256>>>(nullptr, 2, 192, w[l], b[l], 0, 1, -1, out);
        }
        int t = hin; hin = hout; hout = t;
    }
}

// round 8
// speedup vs baseline: 1.9300x; 1.0590x over previous
#include <cuda_runtime.h>
#include <cuda_bf16.h>
#include <math.h>

#define N_NODES 50000
#define N_EDGES 800000
#define IN_DIM  128
#define FEAT    64
#define SCAN_BLOCKS 196   // ceil(50001/256)

typedef unsigned long long u64;

// packed fp32x2 FMA: two IEEE fp32 FMAs per fma-pipe slot (sm_103a FFMA2)
#define FMA_F32X2(d, a, b, c) \
    asm("fma.rn.f32x2 %0, %1, %2, %3;" : "=l"(d) : "l"(a), "l"(b), "l"(c))
#define PACK_DUP_F32X2(out, v) \
    asm("mov.b64 %0, {%1, %1};" : "=l"(out) : "r"(__float_as_uint(v)))

// ---------------- scratch (static device globals; no allocation) ----------------
__device__ float g_H0[N_NODES * FEAT];
__device__ float g_H1[N_NODES * FEAT];
__device__ float g_Agg[N_NODES * 192];   // aggregated messages [N, 3, 64]
__device__ int   g_cnt[N_NODES];
__device__ int   g_off[N_NODES + 1];
__device__ int   g_pos[N_NODES];
__device__ int   g_csr[N_EDGES];
__device__ int   g_bsum[256];

__device__ __forceinline__ float* sel_buf(int s) {
    return (s == 0) ? g_H0 : g_H1;
}

// ---------------- CSR build (once per launch) ----------------
__global__ void zero_cnt_kernel() {
    int i = blockIdx.x * blockDim.x + threadIdx.x;
    if (i < N_NODES) g_cnt[i] = 0;
}
__global__ void count_kernel(const int* __restrict__ ei) {
    int e = blockIdx.x * blockDim.x + threadIdx.x;
    if (e < N_EDGES) atomicAdd(&g_cnt[ei[N_EDGES + e]], 1);
}
__global__ void scan1_kernel() {
    __shared__ int s[256];
    int t = threadIdx.x, i = blockIdx.x * 256 + t;
    int v = (i < N_NODES) ? g_cnt[i] : 0;
    s[t] = v; __syncthreads();
    #pragma unroll
    for (int d = 1; d < 256; d <<= 1) {
        int x = (t >= d) ? s[t - d] : 0;
        __syncthreads();
        s[t] += x;
        __syncthreads();
    }
    if (i < N_NODES) g_off[i] = s[t] - v;
    if (t == 255) g_bsum[blockIdx.x] = s[255];
}
// fused: scan block sums in smem, add to offsets, init cursors, set sentinel
__global__ void scan23_kernel() {
    __shared__ int s[256];
    int t = threadIdx.x;
    s[t] = (t < SCAN_BLOCKS) ? g_bsum[t] : 0;
    __syncthreads();
    #pragma unroll
    for (int d = 1; d < 256; d <<= 1) {
        int x = (t >= d) ? s[t - d] : 0;
        __syncthreads();
        s[t] += x;
        __syncthreads();
    }
    int blk = blockIdx.x;
    int add = (blk == 0) ? 0 : s[blk - 1];       // exclusive prefix of this block
    int i = blk * 256 + t;
    if (i < N_NODES) {
        int o = g_off[i] + add;
        g_off[i] = o;
        g_pos[i] = o;
    }
    if (i == N_NODES) g_off[N_NODES] = N_EDGES;
}
__global__ void fill_csr_kernel(const int* __restrict__ ei) {
    int e = blockIdx.x * blockDim.x + threadIdx.x;
    if (e < N_EDGES) {
        int t = ei[N_EDGES + e];
        int slot = atomicAdd(&g_pos[t], 1);
        g_csr[slot] = e;
    }
}

// ---------------- edge aggregation (warp per node, smem-staged edge data) ----------
// g_Agg[i, c*64+f] = (1/max(deg,1)) * sum_{e in in(i)} ea[e,c] * h[src_e, f]
__global__ void agg_kernel(const int* __restrict__ ei,
                           const float* __restrict__ ea,
                           int hsel)
{
    __shared__ float4 sE[8][32];
    int w = threadIdx.x >> 5;
    int node = blockIdx.x * 8 + w;
    if (node >= N_NODES) return;
    int lane = threadIdx.x & 31;
    const float* H = sel_buf(hsel);
    int off = g_off[node];
    int deg = g_off[node + 1] - off;

    float s0x = 0.f, s0y = 0.f, s1x = 0.f, s1y = 0.f, s2x = 0.f, s2y = 0.f;

    for (int base = 0; base < deg; base += 32) {
        if (base + lane < deg) {
            int eid = __ldg(&g_csr[off + base + lane]);
            int src = __ldg(&ei[eid]);
            float a0 = __ldg(&ea[(size_t)eid * 3 + 0]);
            float a1 = __ldg(&ea[(size_t)eid * 3 + 1]);
            float a2 = __ldg(&ea[(size_t)eid * 3 + 2]);
            sE[w][lane] = make_float4(__int_as_float(src), a0, a1, a2);
        }
        __syncwarp();
        int m = min(32, deg - base);
        for (int k = 0; k < m; k++) {
            float4 ed = sE[w][k];                       // broadcast LDS.128
            int src = __float_as_int(ed.x);
            float2 hv = __ldg(&((const float2*)(H + (size_t)src * 64))[lane]);
            s0x += ed.y * hv.x; s0y += ed.y * hv.y;
            s1x += ed.z * hv.x; s1y += ed.z * hv.y;
            s2x += ed.w * hv.x; s2y += ed.w * hv.y;
        }
        __syncwarp();
    }

    float inv = 1.0f / fmaxf((float)deg, 1.0f);
    float* out = g_Agg + (size_t)node * 192;
    ((float2*)(out      ))[lane] = make_float2(s0x * inv, s0y * inv);
    ((float2*)(out +  64))[lane] = make_float2(s1x * inv, s1y * inv);
    ((float2*)(out + 128))[lane] = make_float2(s2x * inv, s2y * inv);
}

// ---------------- node-side GEMM (FFMA2 inner loop), fused epilogue ----------------
// C[row, o] = sum_k A[row,k] * B[k,o] + bias[o]; optional relu; optional row L2-norm.
// Block: 128 rows x 64 cols, 256 threads, 8x4 register tile (as 8x2 f32x2 pairs).
#define AS_STRIDE 36
__device__ __forceinline__ int arow(int n) { return n * AS_STRIDE + ((n >> 3) << 2); }

__global__ void __launch_bounds__(256)
gemm_nodes(const float* __restrict__ Aext, int asel, int K,
           const float* __restrict__ B, const float* __restrict__ bias,
           int do_relu, int do_norm, int csel, float* __restrict__ extout)
{
    __shared__ float As[128 * AS_STRIDE + 64];
    __shared__ float Ws[32 * 64];

    const float* A = (asel < 0) ? Aext : ((asel == 2) ? g_Agg : sel_buf(asel));
    float* C = (csel < 0) ? extout : sel_buf(csel);

    const int nblk = blockIdx.x * 128;
    const int tid = threadIdx.x;
    const int tx = tid & 15;     // 4 cols each (2 f32x2 pairs)
    const int ty = tid >> 4;     // 8 rows each

    u64 acc2[8][2];
    #pragma unroll
    for (int i = 0; i < 8; i++) { acc2[i][0] = 0ull; acc2[i][1] = 0ull; }

    for (int k0 = 0; k0 < K; k0 += 32) {
        // load A chunk [128 rows x 32 k] row-major (coalesced, conflict-free store)
        #pragma unroll
        for (int i = tid; i < 4096; i += 256) {
            int n = i >> 5, k = i & 31;
            int row = nblk + n;
            As[arow(n) + k] = (row < N_NODES) ? A[(size_t)row * K + k0 + k] : 0.0f;
        }
        // load B chunk [32 k x 64 o]
        #pragma unroll
        for (int i = tid; i < 2048; i += 256) {
            Ws[i] = B[(size_t)(k0 + (i >> 6)) * 64 + (i & 63)];
        }
        __syncthreads();

        #pragma unroll
        for (int kk = 0; kk < 32; kk += 4) {
            float4 a[8];
            #pragma unroll
            for (int i = 0; i < 8; i++)
                a[i] = *(const float4*)&As[arow(ty * 8 + i) + kk];
            #pragma unroll
            for (int q = 0; q < 4; q++) {
                // two packed col-pairs (cols 4tx..4tx+3), 16B-aligned
                ulonglong2 bb = *(const ulonglong2*)&Ws[(kk + q) * 64 + tx * 4];
                #pragma unroll
                for (int i = 0; i < 8; i++) {
                    float av = (q == 0) ? a[i].x : (q == 1) ? a[i].y
                             : (q == 2) ? a[i].z : a[i].w;
                    u64 avv;
                    PACK_DUP_F32X2(avv, av);
                    FMA_F32X2(acc2[i][0], avv, bb.x, acc2[i][0]);
                    FMA_F32X2(acc2[i][1], avv, bb.y, acc2[i][1]);
                }
            }
        }
        __syncthreads();
    }

    float bb[4];
    #pragma unroll
    for (int j = 0; j < 4; j++) bb[j] = __ldg(&bias[tx * 4 + j]);

    #pragma unroll
    for (int i = 0; i < 8; i++) {
        int row = nblk + ty * 8 + i;
        float v[4];
        {
            uint2 p0, p1;
            asm("mov.b64 {%0, %1}, %2;" : "=r"(p0.x), "=r"(p0.y) : "l"(acc2[i][0]));
            asm("mov.b64 {%0, %1}, %2;" : "=r"(p1.x), "=r"(p1.y) : "l"(acc2[i][1]));
            v[0] = __uint_as_float(p0.x); v[1] = __uint_as_float(p0.y);
            v[2] = __uint_as_float(p1.x); v[3] = __uint_as_float(p1.y);
        }
        #pragma unroll
        for (int j = 0; j < 4; j++) {
            v[j] += bb[j];
            if (do_relu) v[j] = fmaxf(v[j], 0.0f);
        }
        if (do_norm) {
            // row's 64 outputs live on the 16 same-ty lanes (a half-warp):
            // shfl_xor masks 1,2,4,8 reduce exactly within that group.
            float ss = v[0] * v[0] + v[1] * v[1] + v[2] * v[2] + v[3] * v[3];
            #pragma unroll
            for (int msk = 1; msk < 16; msk <<= 1)
                ss += __shfl_xor_sync(0xffffffffu, ss, msk);
            float r = 1.0f / fmaxf(sqrtf(ss), 1e-12f);
            #pragma unroll
            for (int j = 0; j < 4; j++) v[j] *= r;
        }
        if (row < N_NODES)
            *(float4*)&C[(size_t)row * 64 + tx * 4] = make_float4(v[0], v[1], v[2], v[3]);
    }
}

// ---------------- launch (kernel launches ONLY — graph-capture safe) ----------------
extern "C" void kernel_launch(void* const* d_in, const int* in_sizes, int n_in,
                              void* d_out, int out_size)
{
    const float* x     = (const float*)d_in[0];
    const int*   ei    = (const int*)  d_in[1];   // [2, E]
    const float* ea    = (const float*)d_in[2];   // [E, 3]
    const float* pre_w = (const float*)d_in[3];   // [128, 64]
    const float* pre_b = (const float*)d_in[4];   // [64]
    const float* w[3]  = {(const float*)d_in[5], (const float*)d_in[7], (const float*)d_in[9]};
    const float* b[3]  = {(const float*)d_in[6], (const float*)d_in[8], (const float*)d_in[10]};
    float* out = (float*)d_out;

    const int gemm_blocks = (N_NODES + 127) / 128;   // 391

    // ---- CSR build (once; graph is fixed per launch) ----
    zero_cnt_kernel<<<(N_NODES + 255) / 256, 256>>>();
    count_kernel<<<(N_EDGES + 255) / 256, 256>>>(ei);
    scan1_kernel<<<SCAN_BLOCKS, 256>>>();
    scan23_kernel<<<SCAN_BLOCKS + 1, 256>>>();   // +1 block covers the sentinel
    fill_csr_kernel<<<(N_EDGES + 255) / 256, 256>>>(ei);

    // linear_pre: H0 = x @ pre_w + pre_b
    gemm_nodes<<<gemm_blocks, 256>>>(x, -1, IN_DIM, pre_w, pre_b, 0, 0, 0, nullptr);

    int hin = 0, hout = 1;
    for (int l = 0; l < 3; l++) {
        // aggregate h (+ mean) -> g_Agg [N, 192]
        agg_kernel<<<(N_NODES + 7) / 8, 256>>>(ei, ea, hin);
        // Hout = g_Agg @ W + b  (+relu for l<2; +L2-normalize into d_out for l==2)
        if (l < 2) {
            gemm_nodes<<<gemm_blocks, 256>>>(nullptr, 2, 192, w[l], b[l], 1, 0, hout, nullptr);
        } else {
            gemm_nodes<<<gemm_blocks, 256>>>(nullptr, 2, 192, w[l], b[l], 0, 1, -1, out);
        }
        int t = hin; hin = hout; hout = t;
    }
}